// round 16
// baseline (speedup 1.0000x reference)
#include <cuda_runtime.h>
#include <cuda_fp16.h>
#include <cstdint>

#define NPTS 1048576
#define BSEG 2048
#define NCTA 148
#define NTHR 256
#define NWARP 8
#define SWEEP 256   // rows per sweep = NWARP * 32

// smem byte offsets (all fp16; weights + acts)
//  W1: [128 o][64 k] SW128 (16KB)
//  W2, W3: 2 k-blocks of [128 o][64 k] (32KB each)
//  ACTF/ACTX: 2 act buffers, each 2 k-blocks of [256 rows][64 cols] fp16 (64KB each)
#define O_W1   0
#define O_W2   16384
#define O_W3   49152
#define O_ACTF 81920
#define O_ACTX 147456
#define O_SEGP 212992
#define O_POOL 213504
#define O_B2   214016
#define O_B3   214528
#define SMEM_BYTES 215040

#define AKB 32768   // act k-block stride (256 rows x 128B)
#define WKB 16384   // weight k-block stride

#define SWZ(x) ((uint32_t)(x) ^ ((((uint32_t)(x)) >> 3) & 0x70))

__device__ __forceinline__ uint32_t smem_u32(const void* p) {
    uint32_t a;
    asm("{ .reg .u64 t; cvta.to.shared.u64 t, %1; cvt.u32.u64 %0, t; }" : "=r"(a) : "l"(p));
    return a;
}
__device__ __forceinline__ void ldsm_x4(uint32_t addr, uint32_t r[4]) {
    asm volatile("ldmatrix.sync.aligned.m8n8.x4.shared.b16 {%0,%1,%2,%3}, [%4];"
        : "=r"(r[0]), "=r"(r[1]), "=r"(r[2]), "=r"(r[3]) : "r"(addr));
}
__device__ __forceinline__ void mma16816(float c[4], const uint32_t a[4], const uint32_t b0, const uint32_t b1) {
    asm volatile("mma.sync.aligned.m16n8k16.row.col.f32.f16.f16.f32 "
        "{%0,%1,%2,%3},{%4,%5,%6,%7},{%8,%9},{%0,%1,%2,%3};"
        : "+f"(c[0]), "+f"(c[1]), "+f"(c[2]), "+f"(c[3])
        : "r"(a[0]), "r"(a[1]), "r"(a[2]), "r"(a[3]), "r"(b0), "r"(b1));
}

// pack two floats -> one fp16x2 word
__device__ __forceinline__ uint32_t packh2(float v0, float v1) {
    __half2 h = __floats2half2_rn(v0, v1);
    return *(uint32_t*)&h;
}

// one layer, TWO 16-row A-tiles x 128 cols per warp: each W fragment feeds 4 MMAs.
template<int KSTEPS>
__device__ __forceinline__ void run_layer2(uint32_t aBase, uint32_t wBase,
                                           int rowbase, int lane,
                                           float acc0[16][4], float acc1[16][4])
{
    const int arow  = rowbase + (lane & 15);
    const int acol  = (lane >> 4) * 8;
    const int wrow  = ((lane >> 4) << 3) + (lane & 7);
    const int wcsel = ((lane >> 3) & 1) << 3;
#pragma unroll
    for (int s = 0; s < KSTEPS; s++) {
        const int kb = s >> 2, kk = (s & 3) * 16;
        uint32_t a0[4], a1[4];
        ldsm_x4(aBase + (uint32_t)kb * AKB + SWZ(arow * 128 + (kk + acol) * 2), a0);
        ldsm_x4(aBase + (uint32_t)kb * AKB + SWZ((arow + 16) * 128 + (kk + acol) * 2), a1);
#pragma unroll
        for (int p8 = 0; p8 < 8; p8++) {
            uint32_t wh[4];
            ldsm_x4(wBase + (uint32_t)kb * WKB + SWZ((p8 * 16 + wrow) * 128 + (kk + wcsel) * 2), wh);
            mma16816(acc0[p8 * 2],     a0, wh[0], wh[1]);
            mma16816(acc0[p8 * 2 + 1], a0, wh[2], wh[3]);
            mma16816(acc1[p8 * 2],     a1, wh[0], wh[1]);
            mma16816(acc1[p8 * 2 + 1], a1, wh[2], wh[3]);
        }
    }
}

// epilogue for one 16-row tile: bias + relu -> fp16 -> swizzled act buffer
__device__ __forceinline__ void epi_store(char* sm_, uint32_t outOff,
                                          const float* bias, float acc[16][4],
                                          int tilebase, int lane)
{
    const int row = tilebase + (lane >> 2);
    const int c0  = 2 * (lane & 3);
#pragma unroll
    for (int nt = 0; nt < 16; nt++) {
        int col = nt * 8 + c0;
        float2 bb = *(const float2*)(bias + col);
        uint32_t kbb = (uint32_t)(col >> 6) * AKB;
        int kk = col & 63;
        *(uint32_t*)(sm_ + outOff + kbb + SWZ(row * 128 + kk * 2)) =
            packh2(fmaxf(acc[nt][0] + bb.x, 0.f), fmaxf(acc[nt][1] + bb.y, 0.f));
        *(uint32_t*)(sm_ + outOff + kbb + SWZ((row + 8) * 128 + kk * 2)) =
            packh2(fmaxf(acc[nt][2] + bb.x, 0.f), fmaxf(acc[nt][3] + bb.y, 0.f));
    }
}

// LDG 16 feature rows (one tile) into 8 float4 regs
__device__ __forceinline__ void load_feats(float4 f[8], const float* __restrict__ feats,
                                           int n0, int hi, int lane)
{
    int n  = n0 + (lane >> 1);
    int k0 = (lane & 1) * 32;
    if (n < hi) {
        const float4* src = (const float4*)(feats + (size_t)n * 64 + k0);
#pragma unroll
        for (int i = 0; i < 8; i++) f[i] = src[i];
    } else {
#pragma unroll
        for (int i = 0; i < 8; i++) f[i] = make_float4(0.f, 0.f, 0.f, 0.f);
    }
}
// STS one tile's rows into buffer k-block 0 (fp16, swizzled)
__device__ __forceinline__ void store_feats(char* sm_, uint32_t bufOff, int tilebase, int lane,
                                            const float4 f[8])
{
    int row = tilebase + (lane >> 1);
    int k0  = (lane & 1) * 32;
#pragma unroll
    for (int i = 0; i < 8; i++) {
        int k = k0 + 4 * i;
        *(uint32_t*)(sm_ + bufOff + SWZ(row * 128 + k * 2))       = packh2(f[i].x, f[i].y);
        *(uint32_t*)(sm_ + bufOff + SWZ(row * 128 + (k + 2) * 2)) = packh2(f[i].z, f[i].w);
    }
}

__global__ void __launch_bounds__(NTHR, 1)
enc_kernel(const float* __restrict__ points, const float* __restrict__ features,
           const int* __restrict__ batch_words,
           const float* __restrict__ w_ne, const float* __restrict__ b_ne,
           const float* __restrict__ w1, const float* __restrict__ b1,
           const float* __restrict__ w2, const float* __restrict__ b2,
           const float* __restrict__ w3, const float* __restrict__ b3,
           const float* __restrict__ wg1, const float* __restrict__ bg1,
           const float* __restrict__ wg2, const float* __restrict__ bg2,
           const float* __restrict__ wg3, const float* __restrict__ bg3,
           float* __restrict__ out)
{
    extern __shared__ char sm[];
    const int tid = threadIdx.x, lane = tid & 31, wid = tid >> 5;
    const int rowbase = wid * 32;             // warp-private 32 rows (2 tiles)
    const uint32_t smb = smem_u32(sm);

    float* segp   = (float*)(sm + O_SEGP);
    int*   pooled = (int*)(sm + O_POOL);
    float* b2s    = (float*)(sm + O_B2);
    float* b3s    = (float*)(sm + O_B3);
    float* actf   = (float*)(sm + O_ACTF);    // pass-1 / head scratch alias

    // ---- stage weights fp16, transposed [o][k], SW128 k-blocks ----
    for (int idx = tid; idx < 8192; idx += NTHR) {         // W1 rows 32..95
        int k = idx >> 7, o = idx & 127;
        *(unsigned short*)(sm + O_W1 + SWZ(o * 128 + k * 2)) =
            __half_as_ushort(__float2half_rn(w1[(32 + k) * 128 + o]));
    }
    for (int idx = tid; idx < 16384; idx += NTHR) {
        int k = idx >> 7, o = idx & 127;
        uint32_t off = (uint32_t)(k >> 6) * WKB + SWZ(o * 128 + (k & 63) * 2);
        *(unsigned short*)(sm + O_W2 + off) = __half_as_ushort(__float2half_rn(w2[k * 128 + o]));
        *(unsigned short*)(sm + O_W3 + off) = __half_as_ushort(__float2half_rn(w3[k * 128 + o]));
    }
    if (tid < 128) { b2s[tid] = b2[tid]; b3s[tid] = b3[tid]; }
    __syncthreads();

    const int stride = (batch_words[NPTS - 1] == 0) ? 2 : 1;   // int64 vs int32

    const int s0 = (blockIdx.x * BSEG) / NCTA;
    const int s1 = ((blockIdx.x + 1) * BSEG) / NCTA;

    for (int b = s0; b < s1; b++) {
        int lo, hi;
        {
            int l = 0, h = NPTS;
            while (l < h) { int m = (l + h) >> 1; if (batch_words[m * stride] < b) l = m + 1; else h = m; }
            lo = l; h = NPTS;
            while (l < h) { int m = (l + h) >> 1; if (batch_words[m * stride] < b + 1) l = m + 1; else h = m; }
            hi = l;
        }

        // ---- pass 1: encoder + segmax -> seg_part ----
        if (tid < 128) pooled[tid] = 0;
        if (tid < 96)  actf[tid] = w_ne[tid];
        if (tid < 32)  actf[96 + tid] = b_ne[tid];
        __syncthreads();
        {
            float em[32];
#pragma unroll
            for (int j = 0; j < 32; j++) em[j] = 0.f;
            const float* wne = actf; const float* bne = actf + 96;
            for (int n = lo + tid; n < hi; n += NTHR) {
                float x = points[3 * n], y = points[3 * n + 1], z = points[3 * n + 2];
#pragma unroll
                for (int j = 0; j < 32; j++)
                    em[j] = fmaxf(em[j], bne[j] + x * wne[j] + y * wne[32 + j] + z * wne[64 + j]);
            }
#pragma unroll
            for (int j = 0; j < 32; j++) {
#pragma unroll
                for (int o = 16; o > 0; o >>= 1)
                    em[j] = fmaxf(em[j], __shfl_xor_sync(0xFFFFFFFFu, em[j], o));
            }
            if (lane == 0) {
#pragma unroll
                for (int j = 0; j < 32; j++) actf[128 + wid * 32 + j] = em[j];
            }
            __syncthreads();
            if (tid < 32) {
                float m = actf[128 + tid];
#pragma unroll
                for (int p = 1; p < NWARP; p++) m = fmaxf(m, actf[128 + p * 32 + tid]);
                actf[512 + tid] = m;
            }
            __syncthreads();
            if (tid < 128) {
                float s = b1[tid];
#pragma unroll
                for (int k = 0; k < 32; k++) s += actf[512 + k] * w1[k * 128 + tid];
                segp[tid] = s;
            }
            __syncthreads();
        }

        // ---- pass 2: 8 warp-private 32-row slices; no mainloop barriers ----
        __half2 rm[16];   // shared by both tiles (same columns)
#pragma unroll
        for (int j = 0; j < 16; j++) rm[j] = __floats2half2_rn(0.f, 0.f);

        uint32_t offF = O_ACTF, offX = O_ACTX;

        int n0 = lo + rowbase;
        if (n0 < hi) {
            {
                float4 f[8];
                load_feats(f, features, n0, hi, lane);
                store_feats(sm, offF, rowbase, lane, f);
                load_feats(f, features, n0 + 16, hi, lane);
                store_feats(sm, offF, rowbase + 16, lane, f);
            }
            __syncwarp();

            for (; n0 < hi; n0 += SWEEP) {
                float acc0[16][4], acc1[16][4];
                // layer 1: K=64, F(kb0) -> X, bias = seg_part
#pragma unroll
                for (int nt = 0; nt < 16; nt++) {
                    acc0[nt][0] = acc0[nt][1] = acc0[nt][2] = acc0[nt][3] = 0.f;
                    acc1[nt][0] = acc1[nt][1] = acc1[nt][2] = acc1[nt][3] = 0.f;
                }
                run_layer2<4>(smb + offF, smb + O_W1, rowbase, lane, acc0, acc1);
                epi_store(sm, offX, segp, acc0, rowbase, lane);
                epi_store(sm, offX, segp, acc1, rowbase + 16, lane);
                __syncwarp();

                // prefetch next sweep's tile-0 features (hidden under L2)
                float4 f[8];
                load_feats(f, features, n0 + SWEEP, hi, lane);

                // layer 2: K=128, X -> F, bias = b2
#pragma unroll
                for (int nt = 0; nt < 16; nt++) {
                    acc0[nt][0] = acc0[nt][1] = acc0[nt][2] = acc0[nt][3] = 0.f;
                    acc1[nt][0] = acc1[nt][1] = acc1[nt][2] = acc1[nt][3] = 0.f;
                }
                run_layer2<8>(smb + offX, smb + O_W2, rowbase, lane, acc0, acc1);
                epi_store(sm, offF, b2s, acc0, rowbase, lane);
                epi_store(sm, offF, b2s, acc1, rowbase + 16, lane);
                __syncwarp();

                // store tile-0 into X kb0; prefetch tile-1 (hidden under L3)
                store_feats(sm, offX, rowbase, lane, f);
                load_feats(f, features, n0 + SWEEP + 16, hi, lane);

                // layer 3: K=128, reads F, bias = b3 -> masked running max (fp16 pairs)
#pragma unroll
                for (int nt = 0; nt < 16; nt++) {
                    acc0[nt][0] = acc0[nt][1] = acc0[nt][2] = acc0[nt][3] = 0.f;
                    acc1[nt][0] = acc1[nt][1] = acc1[nt][2] = acc1[nt][3] = 0.f;
                }
                run_layer2<8>(smb + offF, smb + O_W3, rowbase, lane, acc0, acc1);
                {
                    const int r0 = lane >> 2;
                    const int c0 = 2 * (lane & 3);
                    bool t0v0 = (n0 + r0) < hi,      t0v1 = (n0 + r0 + 8) < hi;
                    bool t1v0 = (n0 + 16 + r0) < hi, t1v1 = (n0 + 16 + r0 + 8) < hi;
#pragma unroll
                    for (int nt = 0; nt < 16; nt++) {
                        int col = nt * 8 + c0;
                        float2 bb = *(const float2*)(b3s + col);
                        if (t0v0) rm[nt] = __hmax2(rm[nt],
                            __floats2half2_rn(acc0[nt][0] + bb.x, acc0[nt][1] + bb.y));
                        if (t0v1) rm[nt] = __hmax2(rm[nt],
                            __floats2half2_rn(acc0[nt][2] + bb.x, acc0[nt][3] + bb.y));
                        if (t1v0) rm[nt] = __hmax2(rm[nt],
                            __floats2half2_rn(acc1[nt][0] + bb.x, acc1[nt][1] + bb.y));
                        if (t1v1) rm[nt] = __hmax2(rm[nt],
                            __floats2half2_rn(acc1[nt][2] + bb.x, acc1[nt][3] + bb.y));
                    }
                }
                // store tile-1 into X kb0 (X not read by anything until next L1)
                store_feats(sm, offX, rowbase + 16, lane, f);
                __syncwarp();
                uint32_t t = offF; offF = offX; offX = t;
            }
        }

        // ---- once per segment: reduce rm across lanes, then atomics ----
#pragma unroll
        for (int j = 0; j < 16; j++) {
#pragma unroll
            for (int o = 4; o < 32; o <<= 1) {
                uint32_t other = __shfl_xor_sync(0xFFFFFFFFu, *(uint32_t*)&rm[j], o);
                rm[j] = __hmax2(rm[j], *(__half2*)&other);
            }
        }
        if (lane < 4) {
#pragma unroll
            for (int nt = 0; nt < 16; nt++) {
                int col = nt * 8 + 2 * lane;
                float2 v = __half22float2(rm[nt]);
                atomicMax(&pooled[col],     __float_as_int(v.x));
                atomicMax(&pooled[col + 1], __float_as_int(v.y));
            }
        }
        __syncthreads();

        // ---- pass 3: head MLP 128 -> 128 -> 64 -> 32 ----
        if (tid < 128) {
            float s = bg1[tid];
#pragma unroll 8
            for (int k = 0; k < 128; k++) s += __int_as_float(pooled[k]) * wg1[k * 128 + tid];
            actf[tid] = fmaxf(s, 0.f);
        }
        __syncthreads();
        if (tid < 64) {
            float s = bg2[tid];
#pragma unroll 8
            for (int k = 0; k < 128; k++) s += actf[k] * wg2[k * 64 + tid];
            actf[128 + tid] = fmaxf(s, 0.f);
        }
        __syncthreads();
        if (tid < 32) {
            float s = bg3[tid];
#pragma unroll 8
            for (int k = 0; k < 64; k++) s += actf[128 + k] * wg3[k * 32 + tid];
            out[b * 32 + tid] = fmaxf(s, 0.f);
        }
        __syncthreads();
    }
}

extern "C" void kernel_launch(void* const* d_in, const int* in_sizes, int n_in,
                              void* d_out, int out_size)
{
    const float* points   = (const float*)d_in[0];
    const float* features = (const float*)d_in[1];
    const int*   batchw   = (const int*)  d_in[2];
    const float* w_ne = (const float*)d_in[3];
    const float* b_ne = (const float*)d_in[4];
    const float* w1   = (const float*)d_in[5];
    const float* b1   = (const float*)d_in[6];
    const float* w2   = (const float*)d_in[7];
    const float* b2   = (const float*)d_in[8];
    const float* w3   = (const float*)d_in[9];
    const float* b3   = (const float*)d_in[10];
    const float* wg1  = (const float*)d_in[11];
    const float* bg1  = (const float*)d_in[12];
    const float* wg2  = (const float*)d_in[13];
    const float* bg2  = (const float*)d_in[14];
    const float* wg3  = (const float*)d_in[15];
    const float* bg3  = (const float*)d_in[16];
    float* out = (float*)d_out;

    cudaFuncSetAttribute(enc_kernel, cudaFuncAttributeMaxDynamicSharedMemorySize, SMEM_BYTES);
    enc_kernel<<<NCTA, NTHR, SMEM_BYTES>>>(
        points, features, batchw,
        w_ne, b_ne, w1, b1, w2, b2, w3, b3,
        wg1, bg1, wg2, bg2, wg3, bg3, out);
}

// round 17
// speedup vs baseline: 1.0752x; 1.0752x over previous
#include <cuda_runtime.h>
#include <cuda_fp16.h>
#include <cstdint>

#define NPTS 1048576
#define BSEG 2048
#define NCTA 148
#define NTHR 384
#define NWARP 12
#define SWEEP 192   // rows per sweep = 6 pairs * 32 rows

// smem byte offsets (all fp16; weights + acts)
//  W1: [128 o][64 k] SW128 (16KB)
//  W2, W3: 2 k-blocks of [128 o][64 k] (32KB each)
//  ACTF/ACTX: 2 act buffers, each 2 k-blocks of [192 rows][64 cols] fp16 (48KB each)
#define O_W1   0
#define O_W2   16384
#define O_W3   49152
#define O_ACTF 81920
#define O_ACTX 131072
#define O_SEGP 180224
#define O_POOL 180736
#define O_B2   181248
#define O_B3   181760
#define SMEM_BYTES 182272

#define AKB 24576   // act k-block stride (192 rows x 128B)
#define WKB 16384   // weight k-block stride

#define SWZ(x) ((uint32_t)(x) ^ ((((uint32_t)(x)) >> 3) & 0x70))

__device__ __forceinline__ uint32_t smem_u32(const void* p) {
    uint32_t a;
    asm("{ .reg .u64 t; cvta.to.shared.u64 t, %1; cvt.u32.u64 %0, t; }" : "=r"(a) : "l"(p));
    return a;
}
__device__ __forceinline__ void ldsm_x4(uint32_t addr, uint32_t r[4]) {
    asm volatile("ldmatrix.sync.aligned.m8n8.x4.shared.b16 {%0,%1,%2,%3}, [%4];"
        : "=r"(r[0]), "=r"(r[1]), "=r"(r[2]), "=r"(r[3]) : "r"(addr));
}
__device__ __forceinline__ void mma16816(float c[4], const uint32_t a[4], const uint32_t b0, const uint32_t b1) {
    asm volatile("mma.sync.aligned.m16n8k16.row.col.f32.f16.f16.f32 "
        "{%0,%1,%2,%3},{%4,%5,%6,%7},{%8,%9},{%0,%1,%2,%3};"
        : "+f"(c[0]), "+f"(c[1]), "+f"(c[2]), "+f"(c[3])
        : "r"(a[0]), "r"(a[1]), "r"(a[2]), "r"(a[3]), "r"(b0), "r"(b1));
}
#define PBAR(p) asm volatile("bar.sync %0, 64;" :: "r"((p) + 1) : "memory")

// pack two floats -> one fp16x2 word
__device__ __forceinline__ uint32_t packh2(float v0, float v1) {
    __half2 h = __floats2half2_rn(v0, v1);
    return *(uint32_t*)&h;
}

// one layer: TWO 16-row A-tiles x 64 cols (half nh) per warp.
// Each W fragment (ldsm_x4) feeds 4 MMAs -> 4x W reuse at 64-reg acc.
template<int KSTEPS>
__device__ __forceinline__ void run_layer2(uint32_t aBase, uint32_t wBase,
                                           int rowbase, int nh, int lane,
                                           float acc0[8][4], float acc1[8][4])
{
    const int arow  = rowbase + (lane & 15);
    const int acol  = (lane >> 4) * 8;
    const int wrow  = nh * 64 + ((lane >> 4) << 3) + (lane & 7);
    const int wcsel = ((lane >> 3) & 1) << 3;
#pragma unroll
    for (int s = 0; s < KSTEPS; s++) {
        const int kb = s >> 2, kk = (s & 3) * 16;
        uint32_t a0[4], a1[4];
        ldsm_x4(aBase + (uint32_t)kb * AKB + SWZ(arow * 128 + (kk + acol) * 2), a0);
        ldsm_x4(aBase + (uint32_t)kb * AKB + SWZ((arow + 16) * 128 + (kk + acol) * 2), a1);
#pragma unroll
        for (int p4 = 0; p4 < 4; p4++) {
            uint32_t wh[4];
            ldsm_x4(wBase + (uint32_t)kb * WKB + SWZ((wrow + p4 * 16) * 128 + (kk + wcsel) * 2), wh);
            mma16816(acc0[p4 * 2],     a0, wh[0], wh[1]);
            mma16816(acc0[p4 * 2 + 1], a0, wh[2], wh[3]);
            mma16816(acc1[p4 * 2],     a1, wh[0], wh[1]);
            mma16816(acc1[p4 * 2 + 1], a1, wh[2], wh[3]);
        }
    }
}

// epilogue for one 16-row tile (warp's 64-col half): bias + relu -> fp16 -> act buffer
__device__ __forceinline__ void epi_store(char* sm_, uint32_t outOff,
                                          const float* bias, float acc[8][4],
                                          int tilebase, int nh, int lane)
{
    const int row = tilebase + (lane >> 2);
    const int c0  = 2 * (lane & 3);
    const uint32_t kbb = (uint32_t)nh * AKB;
#pragma unroll
    for (int nt = 0; nt < 8; nt++) {
        int col = nh * 64 + nt * 8 + c0;
        float2 bb = *(const float2*)(bias + col);
        int kk = col & 63;
        *(uint32_t*)(sm_ + outOff + kbb + SWZ(row * 128 + kk * 2)) =
            packh2(fmaxf(acc[nt][0] + bb.x, 0.f), fmaxf(acc[nt][1] + bb.y, 0.f));
        *(uint32_t*)(sm_ + outOff + kbb + SWZ((row + 8) * 128 + kk * 2)) =
            packh2(fmaxf(acc[nt][2] + bb.x, 0.f), fmaxf(acc[nt][3] + bb.y, 0.f));
    }
}

// LDG 16 feature rows into 8 float4 regs
__device__ __forceinline__ void load_feats(float4 f[8], const float* __restrict__ feats,
                                           int n0, int hi, int lane)
{
    int n  = n0 + (lane >> 1);
    int k0 = (lane & 1) * 32;
    if (n < hi) {
        const float4* src = (const float4*)(feats + (size_t)n * 64 + k0);
#pragma unroll
        for (int i = 0; i < 8; i++) f[i] = src[i];
    } else {
#pragma unroll
        for (int i = 0; i < 8; i++) f[i] = make_float4(0.f, 0.f, 0.f, 0.f);
    }
}
// STS 16 rows into buffer k-block 0 (fp16, swizzled)
__device__ __forceinline__ void store_feats(char* sm_, uint32_t bufOff, int tilebase, int lane,
                                            const float4 f[8])
{
    int row = tilebase + (lane >> 1);
    int k0  = (lane & 1) * 32;
#pragma unroll
    for (int i = 0; i < 8; i++) {
        int k = k0 + 4 * i;
        *(uint32_t*)(sm_ + bufOff + SWZ(row * 128 + k * 2))       = packh2(f[i].x, f[i].y);
        *(uint32_t*)(sm_ + bufOff + SWZ(row * 128 + (k + 2) * 2)) = packh2(f[i].z, f[i].w);
    }
}

__global__ void __launch_bounds__(NTHR, 1)
enc_kernel(const float* __restrict__ points, const float* __restrict__ features,
           const int* __restrict__ batch_words,
           const float* __restrict__ w_ne, const float* __restrict__ b_ne,
           const float* __restrict__ w1, const float* __restrict__ b1,
           const float* __restrict__ w2, const float* __restrict__ b2,
           const float* __restrict__ w3, const float* __restrict__ b3,
           const float* __restrict__ wg1, const float* __restrict__ bg1,
           const float* __restrict__ wg2, const float* __restrict__ bg2,
           const float* __restrict__ wg3, const float* __restrict__ bg3,
           float* __restrict__ out)
{
    extern __shared__ char sm[];
    const int tid = threadIdx.x, lane = tid & 31, wid = tid >> 5;
    const int pair = wid >> 1;                // 6 pairs x 32 rows
    const int nh   = wid & 1;                 // output half (64 cols)
    const int rowbase = pair * 32;
    const uint32_t smb = smem_u32(sm);

    float* segp   = (float*)(sm + O_SEGP);
    int*   pooled = (int*)(sm + O_POOL);
    float* b2s    = (float*)(sm + O_B2);
    float* b3s    = (float*)(sm + O_B3);
    float* actf   = (float*)(sm + O_ACTF);    // pass-1 / head scratch alias

    // ---- stage weights fp16, transposed [o][k], SW128 k-blocks ----
    for (int idx = tid; idx < 8192; idx += NTHR) {         // W1 rows 32..95
        int k = idx >> 7, o = idx & 127;
        *(unsigned short*)(sm + O_W1 + SWZ(o * 128 + k * 2)) =
            __half_as_ushort(__float2half_rn(w1[(32 + k) * 128 + o]));
    }
    for (int idx = tid; idx < 16384; idx += NTHR) {
        int k = idx >> 7, o = idx & 127;
        uint32_t off = (uint32_t)(k >> 6) * WKB + SWZ(o * 128 + (k & 63) * 2);
        *(unsigned short*)(sm + O_W2 + off) = __half_as_ushort(__float2half_rn(w2[k * 128 + o]));
        *(unsigned short*)(sm + O_W3 + off) = __half_as_ushort(__float2half_rn(w3[k * 128 + o]));
    }
    if (tid < 128) { b2s[tid] = b2[tid]; b3s[tid] = b3[tid]; }
    __syncthreads();

    const int stride = (batch_words[NPTS - 1] == 0) ? 2 : 1;   // int64 vs int32

    const int s0 = (blockIdx.x * BSEG) / NCTA;
    const int s1 = ((blockIdx.x + 1) * BSEG) / NCTA;

    for (int b = s0; b < s1; b++) {
        int lo, hi;
        {
            int l = 0, h = NPTS;
            while (l < h) { int m = (l + h) >> 1; if (batch_words[m * stride] < b) l = m + 1; else h = m; }
            lo = l; h = NPTS;
            while (l < h) { int m = (l + h) >> 1; if (batch_words[m * stride] < b + 1) l = m + 1; else h = m; }
            hi = l;
        }

        // ---- pass 1: encoder + segmax -> seg_part ----
        if (tid < 128) pooled[tid] = 0;
        if (tid < 96)  actf[tid] = w_ne[tid];
        if (tid < 32)  actf[96 + tid] = b_ne[tid];
        __syncthreads();
        {
            float em[32];
#pragma unroll
            for (int j = 0; j < 32; j++) em[j] = 0.f;
            const float* wne = actf; const float* bne = actf + 96;
            for (int n = lo + tid; n < hi; n += NTHR) {
                float x = points[3 * n], y = points[3 * n + 1], z = points[3 * n + 2];
#pragma unroll
                for (int j = 0; j < 32; j++)
                    em[j] = fmaxf(em[j], bne[j] + x * wne[j] + y * wne[32 + j] + z * wne[64 + j]);
            }
#pragma unroll
            for (int j = 0; j < 32; j++) {
#pragma unroll
                for (int o = 16; o > 0; o >>= 1)
                    em[j] = fmaxf(em[j], __shfl_xor_sync(0xFFFFFFFFu, em[j], o));
            }
            if (lane == 0) {
#pragma unroll
                for (int j = 0; j < 32; j++) actf[128 + wid * 32 + j] = em[j];
            }
            __syncthreads();
            if (tid < 32) {
                float m = actf[128 + tid];
#pragma unroll
                for (int p = 1; p < NWARP; p++) m = fmaxf(m, actf[128 + p * 32 + tid]);
                actf[640 + tid] = m;
            }
            __syncthreads();
            if (tid < 128) {
                float s = b1[tid];
#pragma unroll
                for (int k = 0; k < 32; k++) s += actf[640 + k] * w1[k * 128 + tid];
                segp[tid] = s;
            }
            __syncthreads();
        }

        // ---- pass 2: 6 pairs x 32 rows; pair barriers only ----
        __half2 rm[8];   // this warp's 64 cols; shared by both tiles
#pragma unroll
        for (int j = 0; j < 8; j++) rm[j] = __floats2half2_rn(0.f, 0.f);

        uint32_t offF = O_ACTF, offX = O_ACTX;

        int n0 = lo + rowbase;
        if (n0 < hi) {
            {   // initial staging: warp stages its own 16 of the pair's 32 rows
                float4 f[8];
                load_feats(f, features, n0 + nh * 16, hi, lane);
                store_feats(sm, offF, rowbase + nh * 16, lane, f);
            }
            PBAR(pair);

            for (; n0 < hi; n0 += SWEEP) {
                float acc0[8][4], acc1[8][4];
                // layer 1: K=64, F(kb0) -> X, bias = seg_part
#pragma unroll
                for (int nt = 0; nt < 8; nt++) {
                    acc0[nt][0] = acc0[nt][1] = acc0[nt][2] = acc0[nt][3] = 0.f;
                    acc1[nt][0] = acc1[nt][1] = acc1[nt][2] = acc1[nt][3] = 0.f;
                }
                run_layer2<4>(smb + offF, smb + O_W1, rowbase, nh, lane, acc0, acc1);
                epi_store(sm, offX, segp, acc0, rowbase, nh, lane);
                epi_store(sm, offX, segp, acc1, rowbase + 16, nh, lane);
                PBAR(pair);

                // prefetch next sweep's features for this warp's 16 rows (hidden by L2)
                float4 f[8];
                load_feats(f, features, n0 + SWEEP + nh * 16, hi, lane);

                // layer 2: K=128, X -> F, bias = b2
#pragma unroll
                for (int nt = 0; nt < 8; nt++) {
                    acc0[nt][0] = acc0[nt][1] = acc0[nt][2] = acc0[nt][3] = 0.f;
                    acc1[nt][0] = acc1[nt][1] = acc1[nt][2] = acc1[nt][3] = 0.f;
                }
                run_layer2<8>(smb + offX, smb + O_W2, rowbase, nh, lane, acc0, acc1);
                epi_store(sm, offF, b2s, acc0, rowbase, nh, lane);
                epi_store(sm, offF, b2s, acc1, rowbase + 16, nh, lane);
                PBAR(pair);   // F complete; X free (both warps done reading X)

                // store next sweep's features into X kb0; overlaps L3 below
                store_feats(sm, offX, rowbase + nh * 16, lane, f);

                // layer 3: K=128, reads F, bias = b3 -> masked running max (fp16 pairs)
#pragma unroll
                for (int nt = 0; nt < 8; nt++) {
                    acc0[nt][0] = acc0[nt][1] = acc0[nt][2] = acc0[nt][3] = 0.f;
                    acc1[nt][0] = acc1[nt][1] = acc1[nt][2] = acc1[nt][3] = 0.f;
                }
                run_layer2<8>(smb + offF, smb + O_W3, rowbase, nh, lane, acc0, acc1);
                {
                    const int r0 = lane >> 2;
                    const int c0 = 2 * (lane & 3);
                    bool t0v0 = (n0 + r0) < hi,      t0v1 = (n0 + r0 + 8) < hi;
                    bool t1v0 = (n0 + 16 + r0) < hi, t1v1 = (n0 + 16 + r0 + 8) < hi;
#pragma unroll
                    for (int nt = 0; nt < 8; nt++) {
                        int col = nh * 64 + nt * 8 + c0;
                        float2 bb = *(const float2*)(b3s + col);
                        if (t0v0) rm[nt] = __hmax2(rm[nt],
                            __floats2half2_rn(acc0[nt][0] + bb.x, acc0[nt][1] + bb.y));
                        if (t0v1) rm[nt] = __hmax2(rm[nt],
                            __floats2half2_rn(acc0[nt][2] + bb.x, acc0[nt][3] + bb.y));
                        if (t1v0) rm[nt] = __hmax2(rm[nt],
                            __floats2half2_rn(acc1[nt][0] + bb.x, acc1[nt][1] + bb.y));
                        if (t1v1) rm[nt] = __hmax2(rm[nt],
                            __floats2half2_rn(acc1[nt][2] + bb.x, acc1[nt][3] + bb.y));
                    }
                }
                PBAR(pair);   // staged X visible + F reads done
                uint32_t t = offF; offF = offX; offX = t;
            }
        }

        // ---- once per segment: reduce rm across lanes, then atomics ----
#pragma unroll
        for (int j = 0; j < 8; j++) {
#pragma unroll
            for (int o = 4; o < 32; o <<= 1) {
                uint32_t other = __shfl_xor_sync(0xFFFFFFFFu, *(uint32_t*)&rm[j], o);
                rm[j] = __hmax2(rm[j], *(__half2*)&other);
            }
        }
        if (lane < 4) {
#pragma unroll
            for (int nt = 0; nt < 8; nt++) {
                int col = nh * 64 + nt * 8 + 2 * lane;
                float2 v = __half22float2(rm[nt]);
                atomicMax(&pooled[col],     __float_as_int(v.x));
                atomicMax(&pooled[col + 1], __float_as_int(v.y));
            }
        }
        __syncthreads();

        // ---- pass 3: head MLP 128 -> 128 -> 64 -> 32 ----
        if (tid < 128) {
            float s = bg1[tid];
#pragma unroll 8
            for (int k = 0; k < 128; k++) s += __int_as_float(pooled[k]) * wg1[k * 128 + tid];
            actf[tid] = fmaxf(s, 0.f);
        }
        __syncthreads();
        if (tid < 64) {
            float s = bg2[tid];
#pragma unroll 8
            for (int k = 0; k < 128; k++) s += actf[k] * wg2[k * 64 + tid];
            actf[128 + tid] = fmaxf(s, 0.f);
        }
        __syncthreads();
        if (tid < 32) {
            float s = bg3[tid];
#pragma unroll 8
            for (int k = 0; k < 64; k++) s += actf[128 + k] * wg3[k * 32 + tid];
            out[b * 32 + tid] = fmaxf(s, 0.f);
        }
        __syncthreads();
    }
}

extern "C" void kernel_launch(void* const* d_in, const int* in_sizes, int n_in,
                              void* d_out, int out_size)
{
    const float* points   = (const float*)d_in[0];
    const float* features = (const float*)d_in[1];
    const int*   batchw   = (const int*)  d_in[2];
    const float* w_ne = (const float*)d_in[3];
    const float* b_ne = (const float*)d_in[4];
    const float* w1   = (const float*)d_in[5];
    const float* b1   = (const float*)d_in[6];
    const float* w2   = (const float*)d_in[7];
    const float* b2   = (const float*)d_in[8];
    const float* w3   = (const float*)d_in[9];
    const float* b3   = (const float*)d_in[10];
    const float* wg1  = (const float*)d_in[11];
    const float* bg1  = (const float*)d_in[12];
    const float* wg2  = (const float*)d_in[13];
    const float* bg2  = (const float*)d_in[14];
    const float* wg3  = (const float*)d_in[15];
    const float* bg3  = (const float*)d_in[16];
    float* out = (float*)d_out;

    cudaFuncSetAttribute(enc_kernel, cudaFuncAttributeMaxDynamicSharedMemorySize, SMEM_BYTES);
    enc_kernel<<<NCTA, NTHR, SMEM_BYTES>>>(
        points, features, batchw,
        w_ne, b_ne, w1, b1, w2, b2, w3, b3,
        wg1, bg1, wg2, bg2, wg3, bg3, out);
}